// round 2
// baseline (speedup 1.0000x reference)
#include <cuda_runtime.h>
#include <math.h>

#define NB 4
#define NN 4096
#define NSQ ((size_t)NN * (size_t)NN)

// ---------------- scratch (device globals: allocation-free) ----------------
__device__ float g_A[(size_t)NB * NSQ];      // 268 MB: S then A (softmaxed in place)
__device__ float g_t[(size_t)NB * 128 * NN]; // 8 MB ping
__device__ float g_y[(size_t)NB * 128 * NN]; // 8 MB conv output (pre-BN)
__device__ float g_x[(size_t)NB * 128 * NN]; // 8 MB pong
__device__ float g_sums[128];
__device__ float g_sumsq[128];
__device__ float g_M[NB * 32 * 32];

// ---------------- gram: S[b,n,m] = sum_c x[b,c,n] * x[b,c,m] ----------------
__global__ __launch_bounds__(256) void gram_kernel(const float* __restrict__ x) {
    __shared__ float sn[32][132];
    __shared__ float sm[32][132];
    const int bxm = blockIdx.x, byn = blockIdx.y, b = blockIdx.z;
    const int tid = threadIdx.x;
    const int tx = tid & 15, ty = tid >> 4;
    const float* xb = x + (size_t)b * 128 * NN;

    float acc[8][8];
#pragma unroll
    for (int u = 0; u < 8; u++)
#pragma unroll
        for (int v = 0; v < 8; v++) acc[u][v] = 0.f;

    for (int kc = 0; kc < 4; kc++) {
        for (int t = tid; t < 32 * 128; t += 256) {
            int k = t >> 7, i = t & 127;
            size_t rowoff = (size_t)(kc * 32 + k) * NN;
            sn[k][i] = xb[rowoff + byn * 128 + i];
            sm[k][i] = xb[rowoff + bxm * 128 + i];
        }
        __syncthreads();
#pragma unroll
        for (int k = 0; k < 32; k++) {
            float4 a0 = *(const float4*)&sn[k][ty * 4];
            float4 a1 = *(const float4*)&sn[k][ty * 4 + 64];
            float4 b0 = *(const float4*)&sm[k][tx * 4];
            float4 b1 = *(const float4*)&sm[k][tx * 4 + 64];
            float av[8] = {a0.x, a0.y, a0.z, a0.w, a1.x, a1.y, a1.z, a1.w};
            float bv[8] = {b0.x, b0.y, b0.z, b0.w, b1.x, b1.y, b1.z, b1.w};
#pragma unroll
            for (int u = 0; u < 8; u++)
#pragma unroll
                for (int v = 0; v < 8; v++) acc[u][v] += av[u] * bv[v];
        }
        __syncthreads();
    }
    float* Cb = g_A + (size_t)b * NSQ;
#pragma unroll
    for (int u = 0; u < 8; u++) {
        int row = (u < 4) ? (ty * 4 + u) : (64 + ty * 4 + (u - 4));
        size_t base = (size_t)(byn * 128 + row) * NN + bxm * 128;
        float4 o0 = make_float4(acc[u][0], acc[u][1], acc[u][2], acc[u][3]);
        float4 o1 = make_float4(acc[u][4], acc[u][5], acc[u][6], acc[u][7]);
        *(float4*)&Cb[base + tx * 4] = o0;
        *(float4*)&Cb[base + tx * 4 + 64] = o1;
    }
}

// ---------------- row softmax on g_A in place (softmax over m) ----------------
__global__ __launch_bounds__(256) void softmax_rows_kernel() {
    __shared__ float buf[NN];
    __shared__ float red[256];
    const int tid = threadIdx.x;
    float* r = g_A + ((size_t)blockIdx.y * NN + blockIdx.x) * NN;

    float mx = -3.4e38f;
    for (int i = tid; i < NN; i += 256) {
        float v = r[i];
        buf[i] = v;
        mx = fmaxf(mx, v);
    }
    red[tid] = mx;
    __syncthreads();
    for (int s = 128; s > 0; s >>= 1) {
        if (tid < s) red[tid] = fmaxf(red[tid], red[tid + s]);
        __syncthreads();
    }
    mx = red[0];
    __syncthreads();

    float sum = 0.f;
    for (int i = tid; i < NN; i += 256) {
        float e = __expf(buf[i] - mx);
        buf[i] = e;
        sum += e;
    }
    red[tid] = sum;
    __syncthreads();
    for (int s = 128; s > 0; s >>= 1) {
        if (tid < s) red[tid] += red[tid + s];
        __syncthreads();
    }
    float inv = 1.f / red[0];
    for (int i = tid; i < NN; i += 256) r[i] = buf[i] * inv;
}

// ---------------- generic row-major GEMM: C = A(MxK) * B(KxNN) ----------------
__global__ __launch_bounds__(256) void gemm_kernel(
    const float* __restrict__ Am, int lda, size_t strideA,
    const float* __restrict__ Bm, size_t strideB,
    float* __restrict__ Cm, size_t strideC,
    int M, int K) {
    __shared__ float As[128][33];
    __shared__ float Bs[32][132];
    const int bx = blockIdx.x, b = blockIdx.z;
    const int tid = threadIdx.x;
    const int tx = tid & 15, ty = tid >> 4;
    const float* Ab = Am + (size_t)b * strideA;
    const float* Bb = Bm + (size_t)b * strideB + bx * 128;
    float acc[8][8];
#pragma unroll
    for (int u = 0; u < 8; u++)
#pragma unroll
        for (int v = 0; v < 8; v++) acc[u][v] = 0.f;

    for (int k0 = 0; k0 < K; k0 += 32) {
        for (int t = tid; t < 128 * 32; t += 256) {
            int i = t >> 5, k = t & 31;
            As[i][k] = (i < M) ? Ab[(size_t)i * lda + k0 + k] : 0.f;
        }
        for (int t = tid; t < 32 * 128; t += 256) {
            int k = t >> 7, j = t & 127;
            Bs[k][j] = Bb[(size_t)(k0 + k) * NN + j];
        }
        __syncthreads();
#pragma unroll
        for (int k = 0; k < 32; k++) {
            float av[8];
#pragma unroll
            for (int u = 0; u < 4; u++) {
                av[u] = As[ty * 4 + u][k];
                av[4 + u] = As[64 + ty * 4 + u][k];
            }
            float4 b0 = *(const float4*)&Bs[k][tx * 4];
            float4 b1 = *(const float4*)&Bs[k][tx * 4 + 64];
            float bv[8] = {b0.x, b0.y, b0.z, b0.w, b1.x, b1.y, b1.z, b1.w};
#pragma unroll
            for (int u = 0; u < 8; u++)
#pragma unroll
                for (int v = 0; v < 8; v++) acc[u][v] += av[u] * bv[v];
        }
        __syncthreads();
    }
    float* Cb = Cm + (size_t)b * strideC + bx * 128;
#pragma unroll
    for (int u = 0; u < 8; u++) {
        int row = (u < 4) ? (ty * 4 + u) : (64 + ty * 4 + (u - 4));
        if (row < M) {
            float4 o0 = make_float4(acc[u][0], acc[u][1], acc[u][2], acc[u][3]);
            float4 o1 = make_float4(acc[u][4], acc[u][5], acc[u][6], acc[u][7]);
            *(float4*)&Cb[(size_t)row * NN + tx * 4] = o0;
            *(float4*)&Cb[(size_t)row * NN + tx * 4 + 64] = o1;
        }
    }
}

// ---------------- per-channel BN statistics over (batch, spatial) ----------------
__global__ __launch_bounds__(256) void stats_kernel(const float* __restrict__ y, int Co) {
    const int o = blockIdx.x;
    const int tid = threadIdx.x;
    float s = 0.f, q = 0.f;
    for (int b = 0; b < NB; b++) {
        const float* p = y + ((size_t)b * Co + o) * NN;
        for (int n = tid; n < NN; n += 256) {
            float v = p[n];
            s += v;
            q += v * v;
        }
    }
    __shared__ float rs[256], rq[256];
    rs[tid] = s;
    rq[tid] = q;
    __syncthreads();
    for (int st = 128; st > 0; st >>= 1) {
        if (tid < st) {
            rs[tid] += rs[tid + st];
            rq[tid] += rq[tid + st];
        }
        __syncthreads();
    }
    if (tid == 0) {
        g_sums[o] = rs[0];
        g_sumsq[o] = rq[0];
    }
}

// ---------------- BN normalize + affine + relu ----------------
__global__ __launch_bounds__(256) void bnrelu_kernel(
    const float* __restrict__ y, const float* __restrict__ gw,
    const float* __restrict__ bw, float* __restrict__ outp, int Co) {
    const int total = NB * Co * NN;
    const float invM = 1.f / (float)(NB * NN);
    for (int idx = blockIdx.x * blockDim.x + threadIdx.x; idx < total;
         idx += gridDim.x * blockDim.x) {
        int o = (idx >> 12) % Co;  // NN == 4096
        float mean = g_sums[o] * invM;
        float var = g_sumsq[o] * invM - mean * mean;
        float sc = rsqrtf(var + 1e-5f) * gw[o];
        float v = (y[idx] - mean) * sc + bw[o];
        outp[idx] = fmaxf(v, 0.f);
    }
}

// ---------------- softmax over 32 channels ----------------
__global__ __launch_bounds__(256) void chsoftmax_kernel(const float* __restrict__ xin,
                                                        float* __restrict__ outp) {
    const int n = blockIdx.x * blockDim.x + threadIdx.x;
    const int b = blockIdx.y;
    const size_t base = (size_t)b * 32 * NN + n;
    float v[32];
    float mx = -3.4e38f;
#pragma unroll
    for (int c = 0; c < 32; c++) {
        v[c] = xin[base + (size_t)c * NN];
        mx = fmaxf(mx, v[c]);
    }
    float s = 0.f;
#pragma unroll
    for (int c = 0; c < 32; c++) {
        float e = __expf(v[c] - mx);
        v[c] = e;
        s += e;
    }
    float inv = 1.f / s;
#pragma unroll
    for (int c = 0; c < 32; c++) outp[base + (size_t)c * NN] = v[c] * inv;
}

// ---------------- M = p p^T, then l = ||I - M||_F ----------------
__global__ __launch_bounds__(256) void zerom_kernel() {
    int i = blockIdx.x * blockDim.x + threadIdx.x;
    if (i < NB * 32 * 32) g_M[i] = 0.f;
}

__global__ __launch_bounds__(1024) void ppt_kernel(const float* __restrict__ p) {
    __shared__ float sp[32][129];
    const int b = blockIdx.y;
    const int nc = blockIdx.x * 128;
    const int tid = threadIdx.x;
    for (int t = tid; t < 32 * 128; t += 1024) {
        int c = t >> 7, n = t & 127;
        sp[c][n] = p[(size_t)b * 32 * NN + (size_t)c * NN + nc + n];
    }
    __syncthreads();
    const int i = tid >> 5, j = tid & 31;
    float acc = 0.f;
#pragma unroll 8
    for (int n = 0; n < 128; n++) acc += sp[i][n] * sp[j][n];
    atomicAdd(&g_M[b * 1024 + tid], acc);
}

__global__ __launch_bounds__(1024) void finalize_kernel(float* __restrict__ outp) {
    const int b = blockIdx.x;
    const int tid = threadIdx.x;
    float m = g_M[b * 1024 + tid];
    float d = (((tid >> 5) == (tid & 31)) ? 1.f : 0.f) - m;
    __shared__ float red[1024];
    red[tid] = d * d;
    __syncthreads();
    for (int s = 512; s > 0; s >>= 1) {
        if (tid < s) red[tid] += red[tid + s];
        __syncthreads();
    }
    if (tid == 0) outp[(size_t)NB * 32 * NN + b] = sqrtf(red[0]);
}

// ---------------- launch ----------------
extern "C" void kernel_launch(void* const* d_in, const int* in_sizes, int n_in,
                              void* d_out, int out_size) {
    const float* x = (const float*)d_in[0];
    const float *w[4], *g[4], *bb[4];

    // setup_inputs() dict order is interleaved: x, w0,g0,b0, w1,g1,b1, w2,g2,b2, w3,g3,b3.
    // Detect via in_sizes (w1 = 16384 elems; g0/b0 = 128) so either layout binds correctly.
    if (n_in >= 13 && in_sizes[2] == 128 && in_sizes[3] == 128 && in_sizes[4] == 16384) {
        // interleaved: w_i, g_i, b_i triples
        for (int i = 0; i < 4; i++) {
            w[i]  = (const float*)d_in[1 + 3 * i];
            g[i]  = (const float*)d_in[2 + 3 * i];
            bb[i] = (const float*)d_in[3 + 3 * i];
        }
    } else {
        // grouped: w0..w3, g0..g3, b0..b3
        for (int i = 0; i < 4; i++) {
            w[i]  = (const float*)d_in[1 + i];
            g[i]  = (const float*)d_in[5 + i];
            bb[i] = (const float*)d_in[9 + i];
        }
    }
    float* out = (float*)d_out;

    float *A, *T, *Y, *X;
    cudaGetSymbolAddress((void**)&A, g_A);
    cudaGetSymbolAddress((void**)&T, g_t);
    cudaGetSymbolAddress((void**)&Y, g_y);
    cudaGetSymbolAddress((void**)&X, g_x);

    const size_t sBig = (size_t)128 * NN;

    // S = x^T x, then softmax rows -> attention A
    gram_kernel<<<dim3(32, 32, NB), 256>>>(x);
    softmax_rows_kernel<<<dim3(NN, NB), 256>>>();

    // layer 0: t = x @ A ; y = w0 t ; BN+relu -> X
    gemm_kernel<<<dim3(32, 1, NB), 256>>>(x, NN, sBig, A, NSQ, T, sBig, 128, NN);
    gemm_kernel<<<dim3(32, 1, NB), 256>>>(w[0], 128, 0, T, sBig, Y, sBig, 128, 128);
    stats_kernel<<<128, 256>>>(Y, 128);
    bnrelu_kernel<<<2048, 256>>>(Y, g[0], bb[0], X, 128);

    // layer 1: t = X @ A ; y = w1 t ; BN+relu -> X
    gemm_kernel<<<dim3(32, 1, NB), 256>>>(X, NN, sBig, A, NSQ, T, sBig, 128, NN);
    gemm_kernel<<<dim3(32, 1, NB), 256>>>(w[1], 128, 0, T, sBig, Y, sBig, 128, 128);
    stats_kernel<<<128, 256>>>(Y, 128);
    bnrelu_kernel<<<2048, 256>>>(Y, g[1], bb[1], X, 128);

    // layer 2: y = w2 X (128->64) ; BN+relu -> T (64ch)
    gemm_kernel<<<dim3(32, 1, NB), 256>>>(w[2], 128, 0, X, sBig, Y, (size_t)64 * NN, 64, 128);
    stats_kernel<<<64, 256>>>(Y, 64);
    bnrelu_kernel<<<1024, 256>>>(Y, g[2], bb[2], T, 64);

    // layer 3: y = w3 T (64->32) ; BN+relu -> X (32ch)
    gemm_kernel<<<dim3(32, 1, NB), 256>>>(w[3], 64, 0, T, (size_t)64 * NN, Y, (size_t)32 * NN, 32, 64);
    stats_kernel<<<32, 256>>>(Y, 32);
    bnrelu_kernel<<<512, 256>>>(Y, g[3], bb[3], X, 32);

    // p = softmax over channels -> out; l = ||I - p p^T||_F per batch
    chsoftmax_kernel<<<dim3(16, NB), 256>>>(X, out);
    zerom_kernel<<<16, 256>>>();
    ppt_kernel<<<dim3(32, NB), 1024>>>(out);
    finalize_kernel<<<NB, 1024>>>(out);
}